// round 15
// baseline (speedup 1.0000x reference)
#include <cuda_runtime.h>
#include <cuda_fp16.h>
#include <math.h>

// ---------------------------------------------------------------------------
// Problem constants
// ---------------------------------------------------------------------------
#define NNODES  10000
#define NHEDGES 512
#define EDIM    128
#define TOPK    32
#define ALPHA   3.0f
#define SENTINEL 0x7FFFFFFF

// ---------------------------------------------------------------------------
// Scratch (device globals -- no runtime allocation allowed)
// ---------------------------------------------------------------------------
#define SK_CMAX 4096
__device__ float          g_nv1[NNODES * EDIM];
__device__ float          g_nv2[NHEDGES * EDIM];
__device__ float          g_H  [NNODES * NHEDGES];          // exact H (fp32)
__device__ __half         g_Hhf[NNODES * NHEDGES];          // fp16(H)
__device__ __half         g_Ahf[(size_t)NNODES * NNODES];   // approx adj (fp16)
__device__ unsigned short g_cand[(size_t)NNODES * SK_CMAX]; // per-row candidates
__device__ int            g_ccnt[NNODES];                   // per-row counts

// ---------------------------------------------------------------------------
// Kernel 1: nodevec (unchanged)
// ---------------------------------------------------------------------------
#define NV_ROWS 8
#define NV_SMEM ((EDIM * EDIM + NV_ROWS * EDIM) * 4)

__global__ void __launch_bounds__(EDIM) nodevec_kernel(
    const float* __restrict__ emb,
    const int*   __restrict__ idx,
    const float* __restrict__ W,
    const float* __restrict__ b,
    float*       __restrict__ out,
    int nrows)
{
    extern __shared__ __align__(16) float nv_smem[];
    float* sW   = nv_smem;
    float* s_in = nv_smem + EDIM * EDIM;

    const int tid = threadIdx.x;
    const int r0  = blockIdx.x * NV_ROWS;

    const float4* Wv  = reinterpret_cast<const float4*>(W);
    float4*       sWv = reinterpret_cast<float4*>(sW);
#pragma unroll
    for (int i = 0; i < (EDIM * EDIM / 4) / EDIM; i++)
        sWv[i * EDIM + tid] = Wv[i * EDIM + tid];

#pragma unroll
    for (int q = 0; q < NV_ROWS; q++) {
        const int r  = r0 + q;
        const int sr = (r < nrows) ? (idx ? idx[r] : r) : 0;
        s_in[q * EDIM + tid] = emb[(size_t)sr * EDIM + tid];
    }
    __syncthreads();

    float acc[NV_ROWS];
    const float bd = b[tid];
#pragma unroll
    for (int q = 0; q < NV_ROWS; q++) acc[q] = bd;

#pragma unroll 4
    for (int k = 0; k < EDIM; k++) {
        const float w = sW[k * EDIM + tid];
#pragma unroll
        for (int q = 0; q < NV_ROWS; q++)
            acc[q] = fmaf(s_in[q * EDIM + k], w, acc[q]);
    }

#pragma unroll
    for (int q = 0; q < NV_ROWS; q++) {
        const int r = r0 + q;
        if (r < nrows)
            out[(size_t)r * EDIM + tid] = tanhf(ALPHA * acc[q]);
    }
}

// ---------------------------------------------------------------------------
// Kernel 2: H (fp32, frozen bit-path) + fp16 copy (unchanged)
// ---------------------------------------------------------------------------
#define GT_TM 128
#define GT_BK 16

__global__ void __launch_bounds__(256, 2) h_gemm_kernel(
    const float* __restrict__ A,
    const float* __restrict__ B,
    float*  __restrict__ C,
    __half* __restrict__ Chf,
    int M, int N, int Kd)
{
    __shared__ __align__(16) float As[2][GT_BK][GT_TM];
    __shared__ __align__(16) float Bs[2][GT_BK][GT_TM];

    const int tid = threadIdx.x;
    const int bm  = blockIdx.y * GT_TM;
    const int bn  = blockIdx.x * GT_TM;
    const int tx  = tid & 15;
    const int ty  = tid >> 4;

    float acc[8][8];
#pragma unroll
    for (int i = 0; i < 8; i++)
#pragma unroll
        for (int j = 0; j < 8; j++) acc[i][j] = 0.0f;

    auto stage = [&](int buf, int k0) {
#pragma unroll
        for (int s = 0; s < 2; s++) {
            const int f  = tid + s * 256;
            const int r  = f >> 2;
            const int kq = (f & 3) << 2;
            const int ga = bm + r;
            float4 va = make_float4(0.f, 0.f, 0.f, 0.f);
            if (ga < M)
                va = *reinterpret_cast<const float4*>(A + (size_t)ga * Kd + k0 + kq);
            As[buf][kq + 0][r] = va.x; As[buf][kq + 1][r] = va.y;
            As[buf][kq + 2][r] = va.z; As[buf][kq + 3][r] = va.w;

            const int gb = bn + r;
            float4 vb = make_float4(0.f, 0.f, 0.f, 0.f);
            if (gb < N)
                vb = *reinterpret_cast<const float4*>(B + (size_t)gb * Kd + k0 + kq);
            Bs[buf][kq + 0][r] = vb.x; Bs[buf][kq + 1][r] = vb.y;
            Bs[buf][kq + 2][r] = vb.z; Bs[buf][kq + 3][r] = vb.w;
        }
    };

    stage(0, 0);
    __syncthreads();

    const int nk = Kd / GT_BK;
    for (int kt = 0; kt < nk; kt++) {
        const int cur = kt & 1;
        if (kt + 1 < nk) stage(cur ^ 1, (kt + 1) * GT_BK);

#pragma unroll
        for (int kk = 0; kk < GT_BK; kk++) {
            float a[8], b[8];
#pragma unroll
            for (int i = 0; i < 8; i += 4)
                *reinterpret_cast<float4*>(&a[i]) =
                    *reinterpret_cast<const float4*>(&As[cur][kk][ty * 8 + i]);
#pragma unroll
            for (int j = 0; j < 8; j += 4)
                *reinterpret_cast<float4*>(&b[j]) =
                    *reinterpret_cast<const float4*>(&Bs[cur][kk][tx * 8 + j]);
#pragma unroll
            for (int i = 0; i < 8; i++)
#pragma unroll
                for (int j = 0; j < 8; j++)
                    acc[i][j] = fmaf(a[i], b[j], acc[i][j]);
        }
        __syncthreads();
    }

#pragma unroll
    for (int i = 0; i < 8; i++) {
        const int gr = bm + ty * 8 + i;
        if (gr >= M) continue;
        float*  crow = C   + (size_t)gr * N;
        __half* hrow = Chf + (size_t)gr * N;
#pragma unroll
        for (int j = 0; j < 8; j += 4) {
            const int gc = bn + tx * 8 + j;
            float4 v;
            v.x = fmaxf(tanhf(ALPHA * acc[i][j + 0]), 0.0f);
            v.y = fmaxf(tanhf(ALPHA * acc[i][j + 1]), 0.0f);
            v.z = fmaxf(tanhf(ALPHA * acc[i][j + 2]), 0.0f);
            v.w = fmaxf(tanhf(ALPHA * acc[i][j + 3]), 0.0f);
            if (gc + 3 < N) {
                *reinterpret_cast<float4*>(crow + gc) = v;
                hrow[gc + 0] = __float2half(v.x);
                hrow[gc + 1] = __float2half(v.y);
                hrow[gc + 2] = __float2half(v.z);
                hrow[gc + 3] = __float2half(v.w);
            } else {
                const float vv[4] = {v.x, v.y, v.z, v.w};
                for (int q = 0; q < 4; q++)
                    if (gc + q < N) {
                        crow[gc + q] = vv[q];
                        hrow[gc + q] = __float2half(vv[q]);
                    }
            }
        }
    }
}

// ---------------------------------------------------------------------------
// Kernel 3: approx adj = fp16( Hhf @ Hhf^T ), fp16 mma.sync + fp32 accum.
// (R13 proven version: K-chunk 64, 72-padded rows; tcgen05 unavailable --
// harness PTX target is sm_103 without the 'a' feature suffix.)
// ---------------------------------------------------------------------------
#define ABKC  64
#define APADK 72
#define AARR  (128 * APADK)
#define ABUF  (2 * AARR)
#define ASMEM (2 * ABUF * 2)

#define LDSM_X4(r, addr) \
    asm volatile("ldmatrix.sync.aligned.m8n8.x4.shared.b16 {%0,%1,%2,%3}, [%4];" \
        : "=r"((r)[0]), "=r"((r)[1]), "=r"((r)[2]), "=r"((r)[3]) : "r"(addr))
#define LDSM_X2(r, addr) \
    asm volatile("ldmatrix.sync.aligned.m8n8.x2.shared.b16 {%0,%1}, [%2];" \
        : "=r"((r)[0]), "=r"((r)[1]) : "r"(addr))
#define MMA_F16(d, a, b) \
    asm volatile("mma.sync.aligned.m16n8k16.row.col.f32.f16.f16.f32 " \
        "{%0,%1,%2,%3},{%4,%5,%6,%7},{%8,%9},{%0,%1,%2,%3};" \
        : "+f"((d)[0]), "+f"((d)[1]), "+f"((d)[2]), "+f"((d)[3]) \
        : "r"((a)[0]), "r"((a)[1]), "r"((a)[2]), "r"((a)[3]), "r"((b)[0]), "r"((b)[1]))

__global__ void __launch_bounds__(256, 2) approx_mma_kernel(
    const __half* __restrict__ Hhf,
    __half* __restrict__ C,
    int M, int Kd)
{
    extern __shared__ __align__(16) unsigned char dynsmem[];
    __half* s = reinterpret_cast<__half*>(dynsmem);

    const int by = blockIdx.y, bx = blockIdx.x;
    if (bx < by) return;
    const int bm  = by * GT_TM, bn = bx * GT_TM;
    const int tid = threadIdx.x;
    const int lane = tid & 31, warp = tid >> 5;
    const int wm = warp >> 2;
    const int wn = warp & 3;

    const unsigned sbase = (unsigned)__cvta_generic_to_shared(s);

    auto stage = [&](int buf, int k0) {
#pragma unroll
        for (int a = 0; a < 2; a++) {
            const int rowbase = (a == 0) ? bm : bn;
#pragma unroll
            for (int sIt = 0; sIt < 4; sIt++) {
                const int idx  = tid + sIt * 256;
                const int row  = idx >> 3;
                const int unit = idx & 7;
                const int grow = rowbase + row;
                const int cpsz = (grow < M) ? 16 : 0;
                const void* src = Hhf + (size_t)(grow < M ? grow : 0) * Kd
                                      + k0 + unit * 8;
                const unsigned dst = sbase +
                    (unsigned)((buf * ABUF + a * AARR + row * APADK + unit * 8) * 2);
                asm volatile("cp.async.cg.shared.global [%0], [%1], 16, %2;\n"
                             :: "r"(dst), "l"(src), "r"(cpsz));
            }
        }
        asm volatile("cp.async.commit_group;\n" ::: "memory");
    };

    float acc[4][4][4];
#pragma unroll
    for (int i = 0; i < 4; i++)
#pragma unroll
        for (int j = 0; j < 4; j++)
#pragma unroll
            for (int q = 0; q < 4; q++) acc[i][j][q] = 0.0f;

    const int nk = Kd / ABKC;   // 8
    stage(0, 0);

    for (int kt = 0; kt < nk; kt++) {
        const int cur = kt & 1;
        if (kt + 1 < nk) {
            stage(cur ^ 1, (kt + 1) * ABKC);
            asm volatile("cp.async.wait_group 1;\n" ::: "memory");
        } else {
            asm volatile("cp.async.wait_group 0;\n" ::: "memory");
        }
        __syncthreads();

        const unsigned bA = sbase + (unsigned)((cur * ABUF + 0 * AARR) * 2);
        const unsigned bB = sbase + (unsigned)((cur * ABUF + 1 * AARR) * 2);

#pragma unroll
        for (int kk = 0; kk < 4; kk++) {
            unsigned ra[4][4], rb[4][2];
            const int arow = wm * 64 + (lane & 15);
            const int acol = kk * 16 + (lane >> 4) * 8;
#pragma unroll
            for (int mf = 0; mf < 4; mf++)
                LDSM_X4(ra[mf], bA + (unsigned)(((arow + mf * 16) * APADK + acol) * 2));
            const int brow = wn * 32 + (lane & 7);
            const int bcol = kk * 16 + ((lane >> 3) & 1) * 8;
#pragma unroll
            for (int nf = 0; nf < 4; nf++)
                LDSM_X2(rb[nf], bB + (unsigned)(((brow + nf * 8) * APADK + bcol) * 2));
#pragma unroll
            for (int mf = 0; mf < 4; mf++)
#pragma unroll
                for (int nf = 0; nf < 4; nf++)
                    MMA_F16(acc[mf][nf], ra[mf], rb[nf]);
        }
        __syncthreads();
    }

    float* Ct = reinterpret_cast<float*>(dynsmem);
#define CT(r, c) Ct[(r) * 133 + (c)]

#pragma unroll
    for (int mf = 0; mf < 4; mf++) {
#pragma unroll
        for (int nf = 0; nf < 4; nf++) {
            const int r0 = wm * 64 + mf * 16 + (lane >> 2);
            const int c0 = wn * 32 + nf * 8 + (lane & 3) * 2;
            const __half h0 = __float2half(acc[mf][nf][0]);
            const __half h1 = __float2half(acc[mf][nf][1]);
            const __half h2 = __float2half(acc[mf][nf][2]);
            const __half h3 = __float2half(acc[mf][nf][3]);
            CT(r0, c0)     = __half2float(h0);
            CT(r0, c0 + 1) = __half2float(h1);
            CT(r0 + 8, c0)     = __half2float(h2);
            CT(r0 + 8, c0 + 1) = __half2float(h3);

            const int gc = bn + c0;
            const int gr0 = bm + r0, gr1 = bm + r0 + 8;
            if (gr0 < M && gc < M) {
                __half2 p; p.x = h0; p.y = h1;
                *reinterpret_cast<__half2*>(C + (size_t)gr0 * M + gc) = p;
            }
            if (gr1 < M && gc < M) {
                __half2 p; p.x = h2; p.y = h3;
                *reinterpret_cast<__half2*>(C + (size_t)gr1 * M + gc) = p;
            }
        }
    }
    __syncthreads();

    for (int i = tid; i < 128 * 128; i += 256) {
        const int r2 = i >> 7;
        const int c2 = i & 127;
        const int gR = bn + r2, gC = bm + c2;
        if (gR < M && gC < M)
            C[(size_t)gR * M + gC] = __float2half(CT(c2, r2));
    }
#undef CT
}

// ---------------------------------------------------------------------------
// Shared helpers: Kth-bin selects (suffix over bin index), 256 threads.
// ---------------------------------------------------------------------------
__device__ __forceinline__ void select256_fn(
    const unsigned* s_hist, unsigned* s_wsum, unsigned* s_wexc,
    int* s_b, int* s_rank, int* s_cnt, int rank_in, int tid)
{
    const int lane = tid & 31, warp = tid >> 5;
    const unsigned h = s_hist[tid];
    unsigned v = h;
#pragma unroll
    for (int off = 1; off < 32; off <<= 1) {
        const unsigned u = __shfl_down_sync(0xFFFFFFFFu, v, off);
        if (lane + off < 32) v += u;
    }
    if (lane == 0) s_wsum[warp] = v;
    __syncthreads();
    if (warp == 0) {
        unsigned wv = (lane < 8) ? s_wsum[lane] : 0u;
#pragma unroll
        for (int off = 1; off < 8; off <<= 1) {
            const unsigned u = __shfl_down_sync(0xFFFFFFFFu, wv, off);
            if (lane + off < 32) wv += u;
        }
        if (lane < 8) s_wexc[lane] = wv - s_wsum[lane];
    }
    __syncthreads();
    {
        const unsigned Sb = s_wexc[warp] + v;
        if ((int)Sb >= rank_in && (int)(Sb - h) < rank_in) {
            *s_b = tid; *s_rank = rank_in - (int)(Sb - h); *s_cnt = (int)h;
        }
    }
    __syncthreads();
}

// 2048 bins; thread tid owns bins [8t .. 8t+7]
__device__ __forceinline__ void select2048_fn(
    const unsigned* s_hist, unsigned* s_wsum, unsigned* s_wexc,
    int* s_b, int* s_rank, int* s_cnt, int rank_in, int tid)
{
    const int lane = tid & 31, warp = tid >> 5;
    unsigned h[8], sfx[8];
#pragma unroll
    for (int q = 0; q < 8; q++) h[q] = s_hist[tid * 8 + q];
    sfx[7] = h[7];
#pragma unroll
    for (int q = 6; q >= 0; q--) sfx[q] = h[q] + sfx[q + 1];
    const unsigned tot = sfx[0];

    unsigned v = tot;
#pragma unroll
    for (int off = 1; off < 32; off <<= 1) {
        const unsigned u = __shfl_down_sync(0xFFFFFFFFu, v, off);
        if (lane + off < 32) v += u;
    }
    if (lane == 0) s_wsum[warp] = v;
    __syncthreads();
    if (warp == 0) {
        unsigned wv = (lane < 8) ? s_wsum[lane] : 0u;
#pragma unroll
        for (int off = 1; off < 8; off <<= 1) {
            const unsigned u = __shfl_down_sync(0xFFFFFFFFu, wv, off);
            if (lane + off < 32) wv += u;
        }
        if (lane < 8) s_wexc[lane] = wv - s_wsum[lane];
    }
    __syncthreads();
    {
        const unsigned excl = s_wexc[warp] + (v - tot);
#pragma unroll
        for (int q = 0; q < 8; q++) {
            const unsigned Sb = sfx[q] + excl;
            if ((int)Sb >= rank_in && (int)(Sb - h[q]) < rank_in) {
                *s_b = tid * 8 + q;
                *s_rank = rank_in - (int)(Sb - h[q]);
                *s_cnt = (int)h[q];
            }
        }
    }
    __syncthreads();
}

__device__ __forceinline__ float key2f(unsigned k) {
    return __half2float(__ushort_as_half((unsigned short)k));
}

// ---------------------------------------------------------------------------
// Kernel 4a: per-row candidate generation + output-row zeroing.
// EXACT a32 via 2-pass fp16-key radix (2048 bins = key>>5, then key&31),
// fused with the row load. cut = a32*0.9965 - 2e-4 (certified superset).
// ---------------------------------------------------------------------------
#define CK_THREADS 256
#define CK_SMEM (NNODES * 2 + 2048 * 4 + 128)

__global__ void __launch_bounds__(CK_THREADS, 6) cand_kernel(
    const __half*   __restrict__ Ahf,
    float*          __restrict__ out,
    unsigned short* __restrict__ cand,
    int*            __restrict__ ccnt,
    int N)
{
    extern __shared__ __align__(16) unsigned char sm[];
    unsigned short* s_apx  = reinterpret_cast<unsigned short*>(sm);          // [N]
    unsigned*       s_hist = reinterpret_cast<unsigned*>(sm + NNODES * 2);   // [2048]
    unsigned*       s_wsum = s_hist + 2048;                                  // [8]
    unsigned*       s_wexc = s_wsum + 8;                                     // [8]
    __shared__ int  s_b, s_rank, s_cnt, s_ccnt;

    const int tid  = threadIdx.x;
    const int lane = tid & 31;
    const int row  = blockIdx.x;
    const size_t abase = (size_t)row * N;
    const unsigned lane_lt = (1u << lane) - 1u;

    // zero the output row
    {
        float4* o4 = reinterpret_cast<float4*>(out + abase);
        const float4 z = make_float4(0.f, 0.f, 0.f, 0.f);
        for (int j = tid; j < N / 4; j += CK_THREADS) o4[j] = z;
    }

    // zero 2048-bin hist
#pragma unroll
    for (int q = 0; q < 2048 / CK_THREADS; q++)
        s_hist[q * CK_THREADS + tid] = 0u;
    __syncthreads();

    // pass 1 (fused with load): bins = key >> 5 (exp + 5 mantissa bits)
    {
        const unsigned* g2 = reinterpret_cast<const unsigned*>(Ahf + abase);
        unsigned*       s2 = reinterpret_cast<unsigned*>(s_apx);
        const int n2 = N / 2;   // N even
        for (int j0 = 0; j0 < n2; j0 += CK_THREADS) {
            const int j = j0 + tid;
            const bool pred = (j < n2);
            unsigned k = 0u;
            if (pred) { k = g2[j]; s2[j] = k; }
            const unsigned act = __ballot_sync(0xFFFFFFFFu, pred);
            if (pred) {
                const unsigned blo = (k & 0xFFFFu) >> 5;
                const unsigned bhi = k >> 21;
                unsigned p = __match_any_sync(act, blo);
                if (lane == (int)(__ffs(p) - 1)) atomicAdd(&s_hist[blo], __popc(p));
                p = __match_any_sync(act, bhi);
                if (lane == (int)(__ffs(p) - 1)) atomicAdd(&s_hist[bhi], __popc(p));
            }
        }
    }
    __syncthreads();

    select2048_fn(s_hist, s_wsum, s_wexc, &s_b, &s_rank, &s_cnt, TOPK, tid);
    const unsigned b1 = (unsigned)s_b;
    const int rank1 = s_rank;
    __syncthreads();

    // pass 2: sub-bins = key & 31, among keys with key>>5 == b1
    if (tid < 256) s_hist[tid] = 0u;
    __syncthreads();
    for (int j = tid; j < N; j += CK_THREADS) {
        const unsigned k = s_apx[j];
        if ((k >> 5) == b1)
            atomicAdd(&s_hist[k & 31u], 1u);
    }
    __syncthreads();
    select256_fn(s_hist, s_wsum, s_wexc, &s_b, &s_rank, &s_cnt, rank1, tid);
    const unsigned a32key = (b1 << 5) | (unsigned)s_b;   // exact 32nd-largest key
    __syncthreads();

    // gather candidates: A >= a32*0.9965 - 2e-4 (certified superset)
    const float cut = key2f(a32key) * 0.9965f - 2e-4f;
    if (tid == 0) s_ccnt = 0;
    __syncthreads();
    unsigned short* crow = cand + (size_t)row * SK_CMAX;
    for (int j0 = 0; j0 < N; j0 += CK_THREADS) {
        const int j = j0 + tid;
        bool pred = false;
        if (j < N)
            pred = (key2f(s_apx[j]) >= cut);
        const unsigned m = __ballot_sync(0xFFFFFFFFu, pred);
        int cb = 0;
        if (lane == 0 && m) cb = atomicAdd(&s_ccnt, __popc(m));
        cb = __shfl_sync(0xFFFFFFFFu, cb, 0);
        if (pred) {
            const int pos = cb + __popc(m & lane_lt);
            if (pos < SK_CMAX) crow[pos] = (unsigned short)j;
        }
    }
    __syncthreads();
    if (tid == 0)
        ccnt[row] = (s_ccnt <= SK_CMAX) ? s_ccnt : SENTINEL;
}

// ---------------------------------------------------------------------------
// Kernel 4b: per-row exact dots (frozen ascending-k fmaf bit chain) + exact
// radix select + jax tie rule + scatter writes (unchanged).
// ---------------------------------------------------------------------------
#define SK_THREADS 256
#define SK_OFF_VAL  2048
#define SK_OFF_CAND 18432
#define SK_OFF_HIST 26688
#define SK_OFF_WS   27712
#define SK_SMEM     27776

__global__ void __launch_bounds__(SK_THREADS, 6) select_kernel(
    const unsigned short* __restrict__ cand,
    const int*            __restrict__ ccnt,
    const float*          __restrict__ H,
    float*                __restrict__ out,
    int N, int Kd)
{
    const int row = blockIdx.x;
    const int cnt = ccnt[row];
    if (cnt == 0 || cnt > SK_CMAX) return;

    extern __shared__ __align__(16) unsigned char sm[];
    float*          s_hrow = reinterpret_cast<float*>(sm);
    float*          s_val  = reinterpret_cast<float*>(sm + SK_OFF_VAL);
    unsigned short* s_cand = reinterpret_cast<unsigned short*>(sm + SK_OFF_CAND);
    unsigned*       s_hist = reinterpret_cast<unsigned*>(sm + SK_OFF_HIST);
    unsigned*       s_wsum = reinterpret_cast<unsigned*>(sm + SK_OFF_WS);
    unsigned*       s_wexc = s_wsum + 8;
    __shared__ int s_b, s_rank, s_cnt;

    const int tid = threadIdx.x;
    const size_t abase = (size_t)row * N;

    if (tid < Kd / 4)
        reinterpret_cast<float4*>(s_hrow)[tid] =
            reinterpret_cast<const float4*>(H + (size_t)row * Kd)[tid];
    {
        const unsigned short* crow = cand + (size_t)row * SK_CMAX;
        for (int c = tid; c < cnt; c += SK_THREADS) s_cand[c] = crow[c];
    }
    __syncthreads();

    for (int c = tid; c < cnt; c += SK_THREADS) {
        const int j = s_cand[c];
        const float4* b4 = reinterpret_cast<const float4*>(H + (size_t)j * Kd);
        float acc = 0.0f;
#pragma unroll 4
        for (int k4 = 0; k4 < NHEDGES / 4; k4++) {
            const float4 bv = __ldg(&b4[k4]);
            const float4 av = *reinterpret_cast<const float4*>(&s_hrow[k4 * 4]);
            acc = fmaf(av.x, bv.x, acc);
            acc = fmaf(av.y, bv.y, acc);
            acc = fmaf(av.z, bv.z, acc);
            acc = fmaf(av.w, bv.w, acc);
        }
        s_val[c] = acc;
    }
    __syncthreads();

    unsigned prefix = 0u;
    int rank = TOPK, cntEq = 0;
    for (int shift = 24; shift >= 0; shift -= 8) {
        s_hist[tid] = 0u;
        __syncthreads();
        const unsigned hm = (shift == 24) ? 0u : (0xFFFFFFFFu << (shift + 8));
        for (int c = tid; c < cnt; c += SK_THREADS) {
            const unsigned k = __float_as_uint(s_val[c]);
            if ((k & hm) == prefix)
                atomicAdd(&s_hist[(k >> shift) & 0xFFu], 1u);
        }
        __syncthreads();
        select256_fn(s_hist, s_wsum, s_wexc, &s_b, &s_rank, &s_cnt, rank, tid);
        prefix |= ((unsigned)s_b << shift);
        rank  = s_rank;
        cntEq = s_cnt;
        __syncthreads();
    }
    const float Tval = __uint_as_float(prefix);

    if (cntEq > rank) {
        if (tid == 0) {
            for (int c = 0; c < cnt; c++)
                if (__float_as_uint(s_val[c]) == prefix) s_val[c] = -2.0f;
            for (int it = 0; it < rank; it++) {
                int bestc = -1, bestj = 0x7FFFFFFF;
                for (int c = 0; c < cnt; c++)
                    if (s_val[c] == -2.0f && (int)s_cand[c] < bestj) {
                        bestj = s_cand[c]; bestc = c;
                    }
                s_val[bestc] = Tval;
            }
            for (int c = 0; c < cnt; c++)
                if (s_val[c] == -2.0f) s_val[c] = -1.0f;
        }
        __syncthreads();
    }

    for (int c = tid; c < cnt; c += SK_THREADS) {
        const float v = s_val[c];
        if (v >= Tval) out[abase + s_cand[c]] = v;
    }
}

// ---------------------------------------------------------------------------
// Kernel 4c: full-exact fallback for sentinel rows (unchanged).
// ---------------------------------------------------------------------------
#define FB_SMEM (NNODES * 4 + NHEDGES * 4 + 256 * 4 + 64)

__global__ void __launch_bounds__(256, 2) fallback_kernel(
    const int*   __restrict__ ccnt,
    const float* __restrict__ H,
    float*       __restrict__ out,
    int N, int Kd)
{
    const int row = blockIdx.x;
    if (ccnt[row] != SENTINEL) return;

    extern __shared__ __align__(16) unsigned char sm[];
    float*    s_row  = reinterpret_cast<float*>(sm);
    float*    s_hrow = reinterpret_cast<float*>(sm + NNODES * 4);
    unsigned* s_hist = reinterpret_cast<unsigned*>(sm + NNODES * 4 + NHEDGES * 4);
    unsigned* s_wsum = s_hist + 256;
    unsigned* s_wexc = s_wsum + 8;
    __shared__ int s_b, s_rank, s_cnt;

    const int tid = threadIdx.x;
    const size_t abase = (size_t)row * N;

    if (tid < Kd / 4)
        reinterpret_cast<float4*>(s_hrow)[tid] =
            reinterpret_cast<const float4*>(H + (size_t)row * Kd)[tid];
    __syncthreads();

    for (int j = tid; j < N; j += 256) {
        const float4* b4 = reinterpret_cast<const float4*>(H + (size_t)j * Kd);
        float acc = 0.0f;
#pragma unroll 4
        for (int k4 = 0; k4 < NHEDGES / 4; k4++) {
            const float4 bv = __ldg(&b4[k4]);
            const float4 av = *reinterpret_cast<const float4*>(&s_hrow[k4 * 4]);
            acc = fmaf(av.x, bv.x, acc);
            acc = fmaf(av.y, bv.y, acc);
            acc = fmaf(av.z, bv.z, acc);
            acc = fmaf(av.w, bv.w, acc);
        }
        s_row[j] = acc;
    }
    __syncthreads();

    unsigned prefix = 0u;
    int rank = TOPK, cntEq = 0;
    for (int shift = 24; shift >= 0; shift -= 8) {
        s_hist[tid] = 0u;
        __syncthreads();
        const unsigned hm = (shift == 24) ? 0u : (0xFFFFFFFFu << (shift + 8));
        for (int j = tid; j < N; j += 256) {
            const unsigned k = __float_as_uint(s_row[j]);
            if ((k & hm) == prefix)
                atomicAdd(&s_hist[(k >> shift) & 0xFFu], 1u);
        }
        __syncthreads();
        select256_fn(s_hist, s_wsum, s_wexc, &s_b, &s_rank, &s_cnt, rank, tid);
        prefix |= ((unsigned)s_b << shift);
        rank  = s_rank;
        cntEq = s_cnt;
        __syncthreads();
    }
    const float Tval = __uint_as_float(prefix);

    if (cntEq > rank) {
        if (tid == 0) {
            int kept = 0;
            for (int j = 0; j < N; j++) {
                if (__float_as_uint(s_row[j]) == prefix) {
                    kept++;
                    if (kept > rank) s_row[j] = -1.0f;
                }
            }
        }
        __syncthreads();
    }

    for (int j = tid; j < N; j += 256) {
        const float v = s_row[j];
        out[abase + j] = (v >= Tval) ? v : 0.0f;
    }
}

// ---------------------------------------------------------------------------
// kernel_launch
// ---------------------------------------------------------------------------
extern "C" void kernel_launch(void* const* d_in, const int* in_sizes, int n_in,
                              void* d_out, int out_size)
{
    (void)in_sizes; (void)n_in; (void)out_size;

    const int*   idx   = (const int*)  d_in[0];
    const float* embn  = (const float*)d_in[1];
    const float* embhe = (const float*)d_in[2];
    const float* W1    = (const float*)d_in[3];
    const float* b1    = (const float*)d_in[4];
    const float* W2    = (const float*)d_in[5];
    const float* b2    = (const float*)d_in[6];
    float*       out   = (float*)d_out;

    float *p_nv1 = nullptr, *p_nv2 = nullptr, *p_H = nullptr;
    __half *p_Hhf = nullptr, *p_Ahf = nullptr;
    unsigned short *p_cand = nullptr;
    int *p_ccnt = nullptr;
    cudaGetSymbolAddress((void**)&p_nv1,  g_nv1);
    cudaGetSymbolAddress((void**)&p_nv2,  g_nv2);
    cudaGetSymbolAddress((void**)&p_H,    g_H);
    cudaGetSymbolAddress((void**)&p_Hhf,  g_Hhf);
    cudaGetSymbolAddress((void**)&p_Ahf,  g_Ahf);
    cudaGetSymbolAddress((void**)&p_cand, g_cand);
    cudaGetSymbolAddress((void**)&p_ccnt, g_ccnt);

    cudaFuncSetAttribute(nodevec_kernel,
                         cudaFuncAttributeMaxDynamicSharedMemorySize, NV_SMEM);
    cudaFuncSetAttribute(approx_mma_kernel,
                         cudaFuncAttributeMaxDynamicSharedMemorySize, ASMEM);
    cudaFuncSetAttribute(cand_kernel,
                         cudaFuncAttributeMaxDynamicSharedMemorySize, CK_SMEM);
    cudaFuncSetAttribute(select_kernel,
                         cudaFuncAttributeMaxDynamicSharedMemorySize, SK_SMEM);
    cudaFuncSetAttribute(fallback_kernel,
                         cudaFuncAttributeMaxDynamicSharedMemorySize, FB_SMEM);

    // 1) nodevecs
    nodevec_kernel<<<NNODES / NV_ROWS, EDIM, NV_SMEM>>>(embn, idx, W1, b1,
                                                        p_nv1, NNODES);
    nodevec_kernel<<<NHEDGES / NV_ROWS, EDIM, NV_SMEM>>>(embhe, nullptr, W2, b2,
                                                         p_nv2, NHEDGES);

    // 2) H (fp32, frozen bit-path) + fp16 copy
    {
        dim3 grid((NHEDGES + GT_TM - 1) / GT_TM, (NNODES + GT_TM - 1) / GT_TM);
        h_gemm_kernel<<<grid, 256>>>(p_nv1, p_nv2, p_H, p_Hhf,
                                     NNODES, NHEDGES, EDIM);
    }

    // 3) approx adj = fp16(Hhf @ Hhf^T), mma.sync K-chunk 64
    {
        const int nt = (NNODES + GT_TM - 1) / GT_TM;
        dim3 grid(nt, nt);
        approx_mma_kernel<<<grid, 256, ASMEM>>>(p_Hhf, p_Ahf, NNODES, NHEDGES);
    }

    // 4) certified top-32 pipeline: candidates -> exact select -> fallback
    cand_kernel<<<NNODES, CK_THREADS, CK_SMEM>>>(p_Ahf, out, p_cand, p_ccnt,
                                                 NNODES);
    select_kernel<<<NNODES, SK_THREADS, SK_SMEM>>>(p_cand, p_ccnt, p_H, out,
                                                   NNODES, NHEDGES);
    fallback_kernel<<<NNODES, 256, FB_SMEM>>>(p_ccnt, p_H, out,
                                              NNODES, NHEDGES);
}

// round 16
// speedup vs baseline: 1.2104x; 1.2104x over previous
#include <cuda_runtime.h>
#include <cuda_fp16.h>
#include <math.h>

// ---------------------------------------------------------------------------
// Problem constants
// ---------------------------------------------------------------------------
#define NNODES  10000
#define NHEDGES 512
#define EDIM    128
#define TOPK    32
#define ALPHA   3.0f
#define SENTINEL 0x7FFFFFFF

// ---------------------------------------------------------------------------
// Scratch (device globals -- no runtime allocation allowed)
// ---------------------------------------------------------------------------
#define SK_CMAX 4096
__device__ float          g_nv1[NNODES * EDIM];
__device__ float          g_nv2[NHEDGES * EDIM];
__device__ float          g_H  [NNODES * NHEDGES];          // exact H (fp32)
__device__ __half         g_Hhf[NNODES * NHEDGES];          // fp16(H)
__device__ __half         g_Ahf[(size_t)NNODES * NNODES];   // approx adj (fp16)
__device__ unsigned short g_cand[(size_t)NNODES * SK_CMAX]; // per-row candidates
__device__ int            g_ccnt[NNODES];                   // per-row counts

// ---------------------------------------------------------------------------
// Kernel 1: nodevec (unchanged)
// ---------------------------------------------------------------------------
#define NV_ROWS 8
#define NV_SMEM ((EDIM * EDIM + NV_ROWS * EDIM) * 4)

__global__ void __launch_bounds__(EDIM) nodevec_kernel(
    const float* __restrict__ emb,
    const int*   __restrict__ idx,
    const float* __restrict__ W,
    const float* __restrict__ b,
    float*       __restrict__ out,
    int nrows)
{
    extern __shared__ __align__(16) float nv_smem[];
    float* sW   = nv_smem;
    float* s_in = nv_smem + EDIM * EDIM;

    const int tid = threadIdx.x;
    const int r0  = blockIdx.x * NV_ROWS;

    const float4* Wv  = reinterpret_cast<const float4*>(W);
    float4*       sWv = reinterpret_cast<float4*>(sW);
#pragma unroll
    for (int i = 0; i < (EDIM * EDIM / 4) / EDIM; i++)
        sWv[i * EDIM + tid] = Wv[i * EDIM + tid];

#pragma unroll
    for (int q = 0; q < NV_ROWS; q++) {
        const int r  = r0 + q;
        const int sr = (r < nrows) ? (idx ? idx[r] : r) : 0;
        s_in[q * EDIM + tid] = emb[(size_t)sr * EDIM + tid];
    }
    __syncthreads();

    float acc[NV_ROWS];
    const float bd = b[tid];
#pragma unroll
    for (int q = 0; q < NV_ROWS; q++) acc[q] = bd;

#pragma unroll 4
    for (int k = 0; k < EDIM; k++) {
        const float w = sW[k * EDIM + tid];
#pragma unroll
        for (int q = 0; q < NV_ROWS; q++)
            acc[q] = fmaf(s_in[q * EDIM + k], w, acc[q]);
    }

#pragma unroll
    for (int q = 0; q < NV_ROWS; q++) {
        const int r = r0 + q;
        if (r < nrows)
            out[(size_t)r * EDIM + tid] = tanhf(ALPHA * acc[q]);
    }
}

// ---------------------------------------------------------------------------
// Kernel 2: H (fp32, frozen bit-path) + fp16 copy (unchanged)
// ---------------------------------------------------------------------------
#define GT_TM 128
#define GT_BK 16

__global__ void __launch_bounds__(256, 2) h_gemm_kernel(
    const float* __restrict__ A,
    const float* __restrict__ B,
    float*  __restrict__ C,
    __half* __restrict__ Chf,
    int M, int N, int Kd)
{
    __shared__ __align__(16) float As[2][GT_BK][GT_TM];
    __shared__ __align__(16) float Bs[2][GT_BK][GT_TM];

    const int tid = threadIdx.x;
    const int bm  = blockIdx.y * GT_TM;
    const int bn  = blockIdx.x * GT_TM;
    const int tx  = tid & 15;
    const int ty  = tid >> 4;

    float acc[8][8];
#pragma unroll
    for (int i = 0; i < 8; i++)
#pragma unroll
        for (int j = 0; j < 8; j++) acc[i][j] = 0.0f;

    auto stage = [&](int buf, int k0) {
#pragma unroll
        for (int s = 0; s < 2; s++) {
            const int f  = tid + s * 256;
            const int r  = f >> 2;
            const int kq = (f & 3) << 2;
            const int ga = bm + r;
            float4 va = make_float4(0.f, 0.f, 0.f, 0.f);
            if (ga < M)
                va = *reinterpret_cast<const float4*>(A + (size_t)ga * Kd + k0 + kq);
            As[buf][kq + 0][r] = va.x; As[buf][kq + 1][r] = va.y;
            As[buf][kq + 2][r] = va.z; As[buf][kq + 3][r] = va.w;

            const int gb = bn + r;
            float4 vb = make_float4(0.f, 0.f, 0.f, 0.f);
            if (gb < N)
                vb = *reinterpret_cast<const float4*>(B + (size_t)gb * Kd + k0 + kq);
            Bs[buf][kq + 0][r] = vb.x; Bs[buf][kq + 1][r] = vb.y;
            Bs[buf][kq + 2][r] = vb.z; Bs[buf][kq + 3][r] = vb.w;
        }
    };

    stage(0, 0);
    __syncthreads();

    const int nk = Kd / GT_BK;
    for (int kt = 0; kt < nk; kt++) {
        const int cur = kt & 1;
        if (kt + 1 < nk) stage(cur ^ 1, (kt + 1) * GT_BK);

#pragma unroll
        for (int kk = 0; kk < GT_BK; kk++) {
            float a[8], b[8];
#pragma unroll
            for (int i = 0; i < 8; i += 4)
                *reinterpret_cast<float4*>(&a[i]) =
                    *reinterpret_cast<const float4*>(&As[cur][kk][ty * 8 + i]);
#pragma unroll
            for (int j = 0; j < 8; j += 4)
                *reinterpret_cast<float4*>(&b[j]) =
                    *reinterpret_cast<const float4*>(&Bs[cur][kk][tx * 8 + j]);
#pragma unroll
            for (int i = 0; i < 8; i++)
#pragma unroll
                for (int j = 0; j < 8; j++)
                    acc[i][j] = fmaf(a[i], b[j], acc[i][j]);
        }
        __syncthreads();
    }

#pragma unroll
    for (int i = 0; i < 8; i++) {
        const int gr = bm + ty * 8 + i;
        if (gr >= M) continue;
        float*  crow = C   + (size_t)gr * N;
        __half* hrow = Chf + (size_t)gr * N;
#pragma unroll
        for (int j = 0; j < 8; j += 4) {
            const int gc = bn + tx * 8 + j;
            float4 v;
            v.x = fmaxf(tanhf(ALPHA * acc[i][j + 0]), 0.0f);
            v.y = fmaxf(tanhf(ALPHA * acc[i][j + 1]), 0.0f);
            v.z = fmaxf(tanhf(ALPHA * acc[i][j + 2]), 0.0f);
            v.w = fmaxf(tanhf(ALPHA * acc[i][j + 3]), 0.0f);
            if (gc + 3 < N) {
                *reinterpret_cast<float4*>(crow + gc) = v;
                hrow[gc + 0] = __float2half(v.x);
                hrow[gc + 1] = __float2half(v.y);
                hrow[gc + 2] = __float2half(v.z);
                hrow[gc + 3] = __float2half(v.w);
            } else {
                const float vv[4] = {v.x, v.y, v.z, v.w};
                for (int q = 0; q < 4; q++)
                    if (gc + q < N) {
                        crow[gc + q] = vv[q];
                        hrow[gc + q] = __float2half(vv[q]);
                    }
            }
        }
    }
}

// ---------------------------------------------------------------------------
// Kernel 3: approx adj = fp16( Hhf @ Hhf^T ), fp16 mma.sync + fp32 accum.
// K-chunk 64, 72-padded rows, 3-STAGE cp.async pipeline (two chunks in
// flight per CTA; wait_group 2 retires only the oldest).
// ---------------------------------------------------------------------------
#define ABKC  64
#define APADK 72
#define AARR  (128 * APADK)
#define ABUF  (2 * AARR)           // one stage: A + B (36864 B)
#define ASMEM (3 * ABUF * 2)       // 110592 B >= epilogue CT 68096

#define LDSM_X4(r, addr) \
    asm volatile("ldmatrix.sync.aligned.m8n8.x4.shared.b16 {%0,%1,%2,%3}, [%4];" \
        : "=r"((r)[0]), "=r"((r)[1]), "=r"((r)[2]), "=r"((r)[3]) : "r"(addr))
#define LDSM_X2(r, addr) \
    asm volatile("ldmatrix.sync.aligned.m8n8.x2.shared.b16 {%0,%1}, [%2];" \
        : "=r"((r)[0]), "=r"((r)[1]) : "r"(addr))
#define MMA_F16(d, a, b) \
    asm volatile("mma.sync.aligned.m16n8k16.row.col.f32.f16.f16.f32 " \
        "{%0,%1,%2,%3},{%4,%5,%6,%7},{%8,%9},{%0,%1,%2,%3};" \
        : "+f"((d)[0]), "+f"((d)[1]), "+f"((d)[2]), "+f"((d)[3]) \
        : "r"((a)[0]), "r"((a)[1]), "r"((a)[2]), "r"((a)[3]), "r"((b)[0]), "r"((b)[1]))

__global__ void __launch_bounds__(256, 2) approx_mma_kernel(
    const __half* __restrict__ Hhf,
    __half* __restrict__ C,
    int M, int Kd)
{
    extern __shared__ __align__(16) unsigned char dynsmem[];
    __half* s = reinterpret_cast<__half*>(dynsmem);

    const int by = blockIdx.y, bx = blockIdx.x;
    if (bx < by) return;
    const int bm  = by * GT_TM, bn = bx * GT_TM;
    const int tid = threadIdx.x;
    const int lane = tid & 31, warp = tid >> 5;
    const int wm = warp >> 2;
    const int wn = warp & 3;

    const unsigned sbase = (unsigned)__cvta_generic_to_shared(s);

    auto stage = [&](int buf, int k0) {
#pragma unroll
        for (int a = 0; a < 2; a++) {
            const int rowbase = (a == 0) ? bm : bn;
#pragma unroll
            for (int sIt = 0; sIt < 4; sIt++) {
                const int idx  = tid + sIt * 256;
                const int row  = idx >> 3;
                const int unit = idx & 7;
                const int grow = rowbase + row;
                const int cpsz = (grow < M) ? 16 : 0;
                const void* src = Hhf + (size_t)(grow < M ? grow : 0) * Kd
                                      + k0 + unit * 8;
                const unsigned dst = sbase +
                    (unsigned)((buf * ABUF + a * AARR + row * APADK + unit * 8) * 2);
                asm volatile("cp.async.cg.shared.global [%0], [%1], 16, %2;\n"
                             :: "r"(dst), "l"(src), "r"(cpsz));
            }
        }
        asm volatile("cp.async.commit_group;\n" ::: "memory");
    };

    float acc[4][4][4];
#pragma unroll
    for (int i = 0; i < 4; i++)
#pragma unroll
        for (int j = 0; j < 4; j++)
#pragma unroll
            for (int q = 0; q < 4; q++) acc[i][j][q] = 0.0f;

    const int nk = Kd / ABKC;   // 8
    stage(0, 0);
    if (nk > 1) stage(1, ABKC);

    for (int kt = 0; kt < nk; kt++) {
        if (kt + 2 < nk) {
            stage((kt + 2) % 3, (kt + 2) * ABKC);
            asm volatile("cp.async.wait_group 2;\n" ::: "memory");
        } else if (kt + 1 < nk) {
            asm volatile("cp.async.wait_group 1;\n" ::: "memory");
        } else {
            asm volatile("cp.async.wait_group 0;\n" ::: "memory");
        }
        __syncthreads();

        const int cur = kt % 3;
        const unsigned bA = sbase + (unsigned)((cur * ABUF + 0 * AARR) * 2);
        const unsigned bB = sbase + (unsigned)((cur * ABUF + 1 * AARR) * 2);

#pragma unroll
        for (int kk = 0; kk < 4; kk++) {
            unsigned ra[4][4], rb[4][2];
            const int arow = wm * 64 + (lane & 15);
            const int acol = kk * 16 + (lane >> 4) * 8;
#pragma unroll
            for (int mf = 0; mf < 4; mf++)
                LDSM_X4(ra[mf], bA + (unsigned)(((arow + mf * 16) * APADK + acol) * 2));
            const int brow = wn * 32 + (lane & 7);
            const int bcol = kk * 16 + ((lane >> 3) & 1) * 8;
#pragma unroll
            for (int nf = 0; nf < 4; nf++)
                LDSM_X2(rb[nf], bB + (unsigned)(((brow + nf * 8) * APADK + bcol) * 2));
#pragma unroll
            for (int mf = 0; mf < 4; mf++)
#pragma unroll
                for (int nf = 0; nf < 4; nf++)
                    MMA_F16(acc[mf][nf], ra[mf], rb[nf]);
        }
        __syncthreads();
    }

    float* Ct = reinterpret_cast<float*>(dynsmem);
#define CT(r, c) Ct[(r) * 133 + (c)]

#pragma unroll
    for (int mf = 0; mf < 4; mf++) {
#pragma unroll
        for (int nf = 0; nf < 4; nf++) {
            const int r0 = wm * 64 + mf * 16 + (lane >> 2);
            const int c0 = wn * 32 + nf * 8 + (lane & 3) * 2;
            const __half h0 = __float2half(acc[mf][nf][0]);
            const __half h1 = __float2half(acc[mf][nf][1]);
            const __half h2 = __float2half(acc[mf][nf][2]);
            const __half h3 = __float2half(acc[mf][nf][3]);
            CT(r0, c0)     = __half2float(h0);
            CT(r0, c0 + 1) = __half2float(h1);
            CT(r0 + 8, c0)     = __half2float(h2);
            CT(r0 + 8, c0 + 1) = __half2float(h3);

            const int gc = bn + c0;
            const int gr0 = bm + r0, gr1 = bm + r0 + 8;
            if (gr0 < M && gc < M) {
                __half2 p; p.x = h0; p.y = h1;
                *reinterpret_cast<__half2*>(C + (size_t)gr0 * M + gc) = p;
            }
            if (gr1 < M && gc < M) {
                __half2 p; p.x = h2; p.y = h3;
                *reinterpret_cast<__half2*>(C + (size_t)gr1 * M + gc) = p;
            }
        }
    }
    __syncthreads();

    for (int i = tid; i < 128 * 128; i += 256) {
        const int r2 = i >> 7;
        const int c2 = i & 127;
        const int gR = bn + r2, gC = bm + c2;
        if (gR < M && gC < M)
            C[(size_t)gR * M + gC] = __float2half(CT(c2, r2));
    }
#undef CT
}

// ---------------------------------------------------------------------------
// Shared helper: 256-bin Kth select (suffix over bin index). 256 threads.
// ---------------------------------------------------------------------------
__device__ __forceinline__ void select256_fn(
    const unsigned* s_hist, unsigned* s_wsum, unsigned* s_wexc,
    int* s_b, int* s_rank, int* s_cnt, int rank_in, int tid)
{
    const int lane = tid & 31, warp = tid >> 5;
    const unsigned h = s_hist[tid];
    unsigned v = h;
#pragma unroll
    for (int off = 1; off < 32; off <<= 1) {
        const unsigned u = __shfl_down_sync(0xFFFFFFFFu, v, off);
        if (lane + off < 32) v += u;
    }
    if (lane == 0) s_wsum[warp] = v;
    __syncthreads();
    if (warp == 0) {
        unsigned wv = (lane < 8) ? s_wsum[lane] : 0u;
#pragma unroll
        for (int off = 1; off < 8; off <<= 1) {
            const unsigned u = __shfl_down_sync(0xFFFFFFFFu, wv, off);
            if (lane + off < 32) wv += u;
        }
        if (lane < 8) s_wexc[lane] = wv - s_wsum[lane];
    }
    __syncthreads();
    {
        const unsigned Sb = s_wexc[warp] + v;
        if ((int)Sb >= rank_in && (int)(Sb - h) < rank_in) {
            *s_b = tid; *s_rank = rank_in - (int)(Sb - h); *s_cnt = (int)h;
        }
    }
    __syncthreads();
}

__device__ __forceinline__ float key2f(unsigned k) {
    return __half2float(__ushort_as_half((unsigned short)k));
}

// ---------------------------------------------------------------------------
// Kernel 4a: per-row candidate generation + output-row zeroing.
// R13 ladder version (proven fastest): conditional-scan histograms, only the
// value tail touches atomics. cut = cutLB*0.9965 - 2e-4 (certified superset).
// ---------------------------------------------------------------------------
#define CK_THREADS 256
#define CK_SMEM (NNODES * 2 + 256 * 4 + 64)

__global__ void __launch_bounds__(CK_THREADS, 6) cand_kernel(
    const __half*   __restrict__ Ahf,
    float*          __restrict__ out,
    unsigned short* __restrict__ cand,
    int*            __restrict__ ccnt,
    int N)
{
    extern __shared__ __align__(16) unsigned char sm[];
    unsigned short* s_apx  = reinterpret_cast<unsigned short*>(sm);
    unsigned*       s_hist = reinterpret_cast<unsigned*>(sm + NNODES * 2);
    unsigned*       s_wsum = s_hist + 256;
    unsigned*       s_wexc = s_wsum + 8;
    __shared__ int   s_b, s_rank, s_cnt, s_ccnt;
    __shared__ float sh_fmax;

    const int tid  = threadIdx.x;
    const int lane = tid & 31;
    const int warp = tid >> 5;
    const int row  = blockIdx.x;
    const size_t abase = (size_t)row * N;
    const unsigned lane_lt = (1u << lane) - 1u;

    {
        float4* o4 = reinterpret_cast<float4*>(out + abase);
        const float4 z = make_float4(0.f, 0.f, 0.f, 0.f);
        for (int j = tid; j < N / 4; j += CK_THREADS) o4[j] = z;
    }

    unsigned um = 0u;
    {
        const uint4* g4 = reinterpret_cast<const uint4*>(Ahf + abase);
        uint4*       s4 = reinterpret_cast<uint4*>(s_apx);
        const int n8 = N / 8;
        for (int j = tid; j < n8; j += CK_THREADS) {
            const uint4 k = g4[j];
            s4[j] = k;
            unsigned ww;
            ww = k.x; um = max(um, ww & 0xFFFFu); um = max(um, ww >> 16);
            ww = k.y; um = max(um, ww & 0xFFFFu); um = max(um, ww >> 16);
            ww = k.z; um = max(um, ww & 0xFFFFu); um = max(um, ww >> 16);
            ww = k.w; um = max(um, ww & 0xFFFFu); um = max(um, ww >> 16);
        }
    }
#pragma unroll
    for (int off = 16; off > 0; off >>= 1)
        um = max(um, __shfl_xor_sync(0xFFFFFFFFu, um, off));
    if (lane == 0) s_wsum[warp] = um;
    __syncthreads();
    if (tid == 0) {
        unsigned m = 0u;
        for (int i = 0; i < CK_THREADS / 32; i++) m = max(m, s_wsum[i]);
        sh_fmax = key2f(m);
    }
    __syncthreads();
    const float vmax = sh_fmax;

    if (vmax <= 0.0f) {
        if (tid == 0) ccnt[row] = 0;
        return;
    }

    float cutLB = -1.0f;
    {
        const float fr[4] = {0.96f, 0.85f, 0.5f, 0.0f};
        for (int at = 0; at < 4; at++) {
            const float lo  = fr[at] * vmax;
            const float rng = vmax - lo;
            const float inv = 256.0f / rng;
            const float wd  = rng * (1.0f / 256.0f);
            s_hist[tid] = 0u;
            if (tid == 0) s_b = -1;
            __syncthreads();
            for (int j = tid; j < N; j += CK_THREADS) {
                const float v = key2f(s_apx[j]);
                if (v >= lo) {
                    int bq = (int)((vmax - v) * inv);
                    bq = 255 - min(bq, 255);
                    atomicAdd(&s_hist[bq], 1u);
                }
            }
            __syncthreads();
            select256_fn(s_hist, s_wsum, s_wexc, &s_b, &s_rank, &s_cnt, TOPK, tid);
            const int found = s_b;
            __syncthreads();
            if (found >= 0) {
                const int u = 255 - found;
                cutLB = vmax - (float)(u + 2) * wd;
                break;
            }
        }
    }
    if (cutLB <= 0.0f) {
        if (tid == 0) ccnt[row] = SENTINEL;
        return;
    }

    const float cut = cutLB * 0.9965f - 2e-4f;
    if (tid == 0) s_ccnt = 0;
    __syncthreads();
    unsigned short* crow = cand + (size_t)row * SK_CMAX;
    for (int j0 = 0; j0 < N; j0 += CK_THREADS) {
        const int j = j0 + tid;
        bool pred = false;
        if (j < N)
            pred = (key2f(s_apx[j]) >= cut);
        const unsigned m = __ballot_sync(0xFFFFFFFFu, pred);
        int cb = 0;
        if (lane == 0 && m) cb = atomicAdd(&s_ccnt, __popc(m));
        cb = __shfl_sync(0xFFFFFFFFu, cb, 0);
        if (pred) {
            const int pos = cb + __popc(m & lane_lt);
            if (pos < SK_CMAX) crow[pos] = (unsigned short)j;
        }
    }
    __syncthreads();
    if (tid == 0)
        ccnt[row] = (s_ccnt <= SK_CMAX) ? s_ccnt : SENTINEL;
}

// ---------------------------------------------------------------------------
// Kernel 4b: per-row exact dots (frozen ascending-k fmaf bit chain) + exact
// radix select + jax tie rule + scatter writes (unchanged from R13).
// ---------------------------------------------------------------------------
#define SK_THREADS 256
#define SK_OFF_VAL  2048
#define SK_OFF_CAND 18432
#define SK_OFF_HIST 26688
#define SK_OFF_WS   27712
#define SK_SMEM     27776

__global__ void __launch_bounds__(SK_THREADS, 6) select_kernel(
    const unsigned short* __restrict__ cand,
    const int*            __restrict__ ccnt,
    const float*          __restrict__ H,
    float*                __restrict__ out,
    int N, int Kd)
{
    const int row = blockIdx.x;
    const int cnt = ccnt[row];
    if (cnt == 0 || cnt > SK_CMAX) return;

    extern __shared__ __align__(16) unsigned char sm[];
    float*          s_hrow = reinterpret_cast<float*>(sm);
    float*          s_val  = reinterpret_cast<float*>(sm + SK_OFF_VAL);
    unsigned short* s_cand = reinterpret_cast<unsigned short*>(sm + SK_OFF_CAND);
    unsigned*       s_hist = reinterpret_cast<unsigned*>(sm + SK_OFF_HIST);
    unsigned*       s_wsum = reinterpret_cast<unsigned*>(sm + SK_OFF_WS);
    unsigned*       s_wexc = s_wsum + 8;
    __shared__ int s_b, s_rank, s_cnt;

    const int tid = threadIdx.x;
    const size_t abase = (size_t)row * N;

    if (tid < Kd / 4)
        reinterpret_cast<float4*>(s_hrow)[tid] =
            reinterpret_cast<const float4*>(H + (size_t)row * Kd)[tid];
    {
        const unsigned short* crow = cand + (size_t)row * SK_CMAX;
        for (int c = tid; c < cnt; c += SK_THREADS) s_cand[c] = crow[c];
    }
    __syncthreads();

    for (int c = tid; c < cnt; c += SK_THREADS) {
        const int j = s_cand[c];
        const float4* b4 = reinterpret_cast<const float4*>(H + (size_t)j * Kd);
        float acc = 0.0f;
#pragma unroll 4
        for (int k4 = 0; k4 < NHEDGES / 4; k4++) {
            const float4 bv = __ldg(&b4[k4]);
            const float4 av = *reinterpret_cast<const float4*>(&s_hrow[k4 * 4]);
            acc = fmaf(av.x, bv.x, acc);
            acc = fmaf(av.y, bv.y, acc);
            acc = fmaf(av.z, bv.z, acc);
            acc = fmaf(av.w, bv.w, acc);
        }
        s_val[c] = acc;
    }
    __syncthreads();

    unsigned prefix = 0u;
    int rank = TOPK, cntEq = 0;
    for (int shift = 24; shift >= 0; shift -= 8) {
        s_hist[tid] = 0u;
        __syncthreads();
        const unsigned hm = (shift == 24) ? 0u : (0xFFFFFFFFu << (shift + 8));
        for (int c = tid; c < cnt; c += SK_THREADS) {
            const unsigned k = __float_as_uint(s_val[c]);
            if ((k & hm) == prefix)
                atomicAdd(&s_hist[(k >> shift) & 0xFFu], 1u);
        }
        __syncthreads();
        select256_fn(s_hist, s_wsum, s_wexc, &s_b, &s_rank, &s_cnt, rank, tid);
        prefix |= ((unsigned)s_b << shift);
        rank  = s_rank;
        cntEq = s_cnt;
        __syncthreads();
    }
    const float Tval = __uint_as_float(prefix);

    if (cntEq > rank) {
        if (tid == 0) {
            for (int c = 0; c < cnt; c++)
                if (__float_as_uint(s_val[c]) == prefix) s_val[c] = -2.0f;
            for (int it = 0; it < rank; it++) {
                int bestc = -1, bestj = 0x7FFFFFFF;
                for (int c = 0; c < cnt; c++)
                    if (s_val[c] == -2.0f && (int)s_cand[c] < bestj) {
                        bestj = s_cand[c]; bestc = c;
                    }
                s_val[bestc] = Tval;
            }
            for (int c = 0; c < cnt; c++)
                if (s_val[c] == -2.0f) s_val[c] = -1.0f;
        }
        __syncthreads();
    }

    for (int c = tid; c < cnt; c += SK_THREADS) {
        const float v = s_val[c];
        if (v >= Tval) out[abase + s_cand[c]] = v;
    }
}

// ---------------------------------------------------------------------------
// Kernel 4c: full-exact fallback for sentinel rows (unchanged).
// ---------------------------------------------------------------------------
#define FB_SMEM (NNODES * 4 + NHEDGES * 4 + 256 * 4 + 64)

__global__ void __launch_bounds__(256, 2) fallback_kernel(
    const int*   __restrict__ ccnt,
    const float* __restrict__ H,
    float*       __restrict__ out,
    int N, int Kd)
{
    const int row = blockIdx.x;
    if (ccnt[row] != SENTINEL) return;

    extern __shared__ __align__(16) unsigned char sm[];
    float*    s_row  = reinterpret_cast<float*>(sm);
    float*    s_hrow = reinterpret_cast<float*>(sm + NNODES * 4);
    unsigned* s_hist = reinterpret_cast<unsigned*>(sm + NNODES * 4 + NHEDGES * 4);
    unsigned* s_wsum = s_hist + 256;
    unsigned* s_wexc = s_wsum + 8;
    __shared__ int s_b, s_rank, s_cnt;

    const int tid = threadIdx.x;
    const size_t abase = (size_t)row * N;

    if (tid < Kd / 4)
        reinterpret_cast<float4*>(s_hrow)[tid] =
            reinterpret_cast<const float4*>(H + (size_t)row * Kd)[tid];
    __syncthreads();

    for (int j = tid; j < N; j += 256) {
        const float4* b4 = reinterpret_cast<const float4*>(H + (size_t)j * Kd);
        float acc = 0.0f;
#pragma unroll 4
        for (int k4 = 0; k4 < NHEDGES / 4; k4++) {
            const float4 bv = __ldg(&b4[k4]);
            const float4 av = *reinterpret_cast<const float4*>(&s_hrow[k4 * 4]);
            acc = fmaf(av.x, bv.x, acc);
            acc = fmaf(av.y, bv.y, acc);
            acc = fmaf(av.z, bv.z, acc);
            acc = fmaf(av.w, bv.w, acc);
        }
        s_row[j] = acc;
    }
    __syncthreads();

    unsigned prefix = 0u;
    int rank = TOPK, cntEq = 0;
    for (int shift = 24; shift >= 0; shift -= 8) {
        s_hist[tid] = 0u;
        __syncthreads();
        const unsigned hm = (shift == 24) ? 0u : (0xFFFFFFFFu << (shift + 8));
        for (int j = tid; j < N; j += 256) {
            const unsigned k = __float_as_uint(s_row[j]);
            if ((k & hm) == prefix)
                atomicAdd(&s_hist[(k >> shift) & 0xFFu], 1u);
        }
        __syncthreads();
        select256_fn(s_hist, s_wsum, s_wexc, &s_b, &s_rank, &s_cnt, rank, tid);
        prefix |= ((unsigned)s_b << shift);
        rank  = s_rank;
        cntEq = s_cnt;
        __syncthreads();
    }
    const float Tval = __uint_as_float(prefix);

    if (cntEq > rank) {
        if (tid == 0) {
            int kept = 0;
            for (int j = 0; j < N; j++) {
                if (__float_as_uint(s_row[j]) == prefix) {
                    kept++;
                    if (kept > rank) s_row[j] = -1.0f;
                }
            }
        }
        __syncthreads();
    }

    for (int j = tid; j < N; j += 256) {
        const float v = s_row[j];
        out[abase + j] = (v >= Tval) ? v : 0.0f;
    }
}

// ---------------------------------------------------------------------------
// kernel_launch
// ---------------------------------------------------------------------------
extern "C" void kernel_launch(void* const* d_in, const int* in_sizes, int n_in,
                              void* d_out, int out_size)
{
    (void)in_sizes; (void)n_in; (void)out_size;

    const int*   idx   = (const int*)  d_in[0];
    const float* embn  = (const float*)d_in[1];
    const float* embhe = (const float*)d_in[2];
    const float* W1    = (const float*)d_in[3];
    const float* b1    = (const float*)d_in[4];
    const float* W2    = (const float*)d_in[5];
    const float* b2    = (const float*)d_in[6];
    float*       out   = (float*)d_out;

    float *p_nv1 = nullptr, *p_nv2 = nullptr, *p_H = nullptr;
    __half *p_Hhf = nullptr, *p_Ahf = nullptr;
    unsigned short *p_cand = nullptr;
    int *p_ccnt = nullptr;
    cudaGetSymbolAddress((void**)&p_nv1,  g_nv1);
    cudaGetSymbolAddress((void**)&p_nv2,  g_nv2);
    cudaGetSymbolAddress((void**)&p_H,    g_H);
    cudaGetSymbolAddress((void**)&p_Hhf,  g_Hhf);
    cudaGetSymbolAddress((void**)&p_Ahf,  g_Ahf);
    cudaGetSymbolAddress((void**)&p_cand, g_cand);
    cudaGetSymbolAddress((void**)&p_ccnt, g_ccnt);

    cudaFuncSetAttribute(nodevec_kernel,
                         cudaFuncAttributeMaxDynamicSharedMemorySize, NV_SMEM);
    cudaFuncSetAttribute(approx_mma_kernel,
                         cudaFuncAttributeMaxDynamicSharedMemorySize, ASMEM);
    cudaFuncSetAttribute(cand_kernel,
                         cudaFuncAttributeMaxDynamicSharedMemorySize, CK_SMEM);
    cudaFuncSetAttribute(select_kernel,
                         cudaFuncAttributeMaxDynamicSharedMemorySize, SK_SMEM);
    cudaFuncSetAttribute(fallback_kernel,
                         cudaFuncAttributeMaxDynamicSharedMemorySize, FB_SMEM);

    // 1) nodevecs
    nodevec_kernel<<<NNODES / NV_ROWS, EDIM, NV_SMEM>>>(embn, idx, W1, b1,
                                                        p_nv1, NNODES);
    nodevec_kernel<<<NHEDGES / NV_ROWS, EDIM, NV_SMEM>>>(embhe, nullptr, W2, b2,
                                                         p_nv2, NHEDGES);

    // 2) H (fp32, frozen bit-path) + fp16 copy
    {
        dim3 grid((NHEDGES + GT_TM - 1) / GT_TM, (NNODES + GT_TM - 1) / GT_TM);
        h_gemm_kernel<<<grid, 256>>>(p_nv1, p_nv2, p_H, p_Hhf,
                                     NNODES, NHEDGES, EDIM);
    }

    // 3) approx adj = fp16(Hhf @ Hhf^T), mma.sync K-chunk 64, 3-stage pipe
    {
        const int nt = (NNODES + GT_TM - 1) / GT_TM;
        dim3 grid(nt, nt);
        approx_mma_kernel<<<grid, 256, ASMEM>>>(p_Hhf, p_Ahf, NNODES, NHEDGES);
    }

    // 4) certified top-32 pipeline: candidates -> exact select -> fallback
    cand_kernel<<<NNODES, CK_THREADS, CK_SMEM>>>(p_Ahf, out, p_cand, p_ccnt,
                                                 NNODES);
    select_kernel<<<NNODES, SK_THREADS, SK_SMEM>>>(p_cand, p_ccnt, p_H, out,
                                                   NNODES, NHEDGES);
    fallback_kernel<<<NNODES, 256, FB_SMEM>>>(p_ccnt, p_H, out,
                                              NNODES, NHEDGES);
}